// round 4
// baseline (speedup 1.0000x reference)
#include <cuda_runtime.h>
#include <cstdint>
#include <cstddef>

#define TM      64      // rows per CTA
#define NT      512     // threads per CTA (16 warps)
#define KC      32      // k-chunk
#define LATENT  256
#define NNODES  256
#define NROWS   65536
#define ZP      66      // u64 stride for duplicated-pair Z tile (even -> LDS.128 aligned)
#define ES      258     // float stride for E tile (even -> LDS.64 aligned)
#define STAGE_FLOATS (KC*ZP*2 + KC*ES)   // 4224 + 8256 = 12480 floats
#define REDS    33
#define EPSF    1.1920929e-7f

typedef unsigned long long u64;

__device__ __forceinline__ u64 ffma2(u64 a, u64 b, u64 c) {
    u64 d;
    asm("fma.rn.f32x2 %0, %1, %2, %3;" : "=l"(d) : "l"(a), "l"(b), "l"(c));
    return d;
}
__device__ __forceinline__ u64 pack2(float x) {
    u64 d;
    asm("mov.b64 %0, {%1, %1};" : "=l"(d) : "f"(x));
    return d;
}
__device__ __forceinline__ u64 packf2(float lo, float hi) {
    u64 d;
    asm("mov.b64 %0, {%1, %2};" : "=l"(d) : "f"(lo), "f"(hi));
    return d;
}

extern __shared__ float smf[];

// smem: two stages [0 .. 2*12480 floats); tail: e2(256) z2(64) bmu(64) rqs(64)
// reduction arrays (64*33 *3) overlay stage0 after the GEMM.
#define SMEM_FLOATS (2*STAGE_FLOATS + 256 + 64 + 64 + 64)
#define SMEM_BYTES  (SMEM_FLOATS * 4)

__global__ void __launch_bounds__(NT, 1)
som_kernel(const float* __restrict__ Z, const float* __restrict__ E,
           const int* __restrict__ Alpha, float* __restrict__ out)
{
    float* e2   = smf + 2 * STAGE_FLOATS;
    float* z2   = e2 + NNODES;
    int*   bmuS = (int*)(z2 + TM);
    float* rqs  = (float*)(bmuS + TM);
    float* redv = smf;                       // overlays stage0 (dead post-GEMM)
    int*   redi = (int*)(smf + TM * REDS);
    float* reds = smf + 2 * TM * REDS;

    const int t  = threadIdx.x;
    const int R0 = blockIdx.x * TM;
    const int cg = t & 31;       // node lane: pairs {2cg, 2cg+64, 2cg+128, 2cg+192}
    const int rg = t >> 5;       // 16 row groups of 4 rows
    const int r0 = rg * 4;

    // ---- e2[j] = ||e_j||^2 (L2-resident) ----
    if (t < NNODES) {
        const float4* er4 = (const float4*)(E + (size_t)t * LATENT);
        float s = 0.f;
        #pragma unroll 8
        for (int i = 0; i < 64; i++) { float4 v = er4[i]; s += v.x*v.x + v.y*v.y + v.z*v.z + v.w*v.w; }
        e2[t] = s;
    }

    // ---- gmem prefetch mapping ----
    // Z: 1 float4/thread/chunk (64 rows x 8 kq), coalesced
    const int zrow = t >> 3, zkq = t & 7;
    // E: 4 float4/thread/chunk, lane-per-node (L2-resident)
    const int enode = t & 255;
    const int ekq0  = t >> 8;            // kq slices {ekq0, ekq0+2, ekq0+4, ekq0+6}

    u64 acc[4][4];
    #pragma unroll
    for (int r = 0; r < 4; r++)
        #pragma unroll
        for (int m = 0; m < 4; m++) acc[r][m] = 0ull;

    // prologue: chunk 0 gmem loads
    float4 zr = *(const float4*)(Z + (size_t)(R0 + zrow) * LATENT + zkq * 4);
    float4 er[4];
    #pragma unroll
    for (int i = 0; i < 4; i++)
        er[i] = *(const float4*)(E + (size_t)enode * LATENT + (ekq0 + 2 * i) * 4);

    float z2r = 0.f;

    for (int c = 0; c < LATENT / KC; c++) {
        u64*   zs2 = (u64*)(smf + (c & 1) * STAGE_FLOATS);
        float* es  = smf + (c & 1) * STAGE_FLOATS + KC * ZP * 2;

        // store prefetched regs -> this stage (Z duplicated as {z,z} u64 pairs)
        {
            u64* p = zs2 + (size_t)(4 * zkq) * ZP + zrow;
            p[0]      = pack2(zr.x);
            p[ZP]     = pack2(zr.y);
            p[2 * ZP] = pack2(zr.z);
            p[3 * ZP] = pack2(zr.w);
            #pragma unroll
            for (int i = 0; i < 4; i++) {
                float* q = es + (size_t)(4 * (ekq0 + 2 * i)) * ES + enode;
                q[0] = er[i].x; q[ES] = er[i].y; q[2*ES] = er[i].z; q[3*ES] = er[i].w;
            }
        }
        __syncthreads();

        // issue next chunk's gmem loads (hidden behind this chunk's compute)
        if (c < LATENT / KC - 1) {
            int cb = (c + 1) * KC;
            zr = *(const float4*)(Z + (size_t)(R0 + zrow) * LATENT + cb + zkq * 4);
            #pragma unroll
            for (int i = 0; i < 4; i++)
                er[i] = *(const float4*)(E + (size_t)enode * LATENT + cb + (ekq0 + 2 * i) * 4);
        }

        // z2 partial (thread t owns row t; reads low float of duplicated pair)
        if (t < TM) {
            #pragma unroll 8
            for (int k = 0; k < KC; k++) {
                float v = *((const float*)(zs2 + (size_t)k * ZP + t));
                z2r = fmaf(v, v, z2r);
            }
        }

        // inner GEMM, register double-buffered over k: 4 rows x 4 node-pairs
        u64 zA[4], eA[4], zB[4], eB[4];
        {
            const ulonglong2* zp = (const ulonglong2*)(zs2 + r0);
            ulonglong2 a0 = zp[0], a1 = zp[1];
            zA[0] = a0.x; zA[1] = a0.y; zA[2] = a1.x; zA[3] = a1.y;
            const float* ek = es + 2 * cg;
            eA[0] = *(const u64*)(ek);
            eA[1] = *(const u64*)(ek + 64);
            eA[2] = *(const u64*)(ek + 128);
            eA[3] = *(const u64*)(ek + 192);
        }
        #pragma unroll
        for (int k = 0; k < KC; k += 2) {
            // prefetch k+1 into B
            {
                const ulonglong2* zp = (const ulonglong2*)(zs2 + (size_t)(k + 1) * ZP + r0);
                ulonglong2 a0 = zp[0], a1 = zp[1];
                zB[0] = a0.x; zB[1] = a0.y; zB[2] = a1.x; zB[3] = a1.y;
                const float* ek = es + (size_t)(k + 1) * ES + 2 * cg;
                eB[0] = *(const u64*)(ek);
                eB[1] = *(const u64*)(ek + 64);
                eB[2] = *(const u64*)(ek + 128);
                eB[3] = *(const u64*)(ek + 192);
            }
            #pragma unroll
            for (int r = 0; r < 4; r++) {
                acc[r][0] = ffma2(zA[r], eA[0], acc[r][0]);
                acc[r][1] = ffma2(zA[r], eA[1], acc[r][1]);
                acc[r][2] = ffma2(zA[r], eA[2], acc[r][2]);
                acc[r][3] = ffma2(zA[r], eA[3], acc[r][3]);
            }
            // prefetch k+2 into A
            if (k + 2 < KC) {
                const ulonglong2* zp = (const ulonglong2*)(zs2 + (size_t)(k + 2) * ZP + r0);
                ulonglong2 a0 = zp[0], a1 = zp[1];
                zA[0] = a0.x; zA[1] = a0.y; zA[2] = a1.x; zA[3] = a1.y;
                const float* ek = es + (size_t)(k + 2) * ES + 2 * cg;
                eA[0] = *(const u64*)(ek);
                eA[1] = *(const u64*)(ek + 64);
                eA[2] = *(const u64*)(ek + 128);
                eA[3] = *(const u64*)(ek + 192);
            }
            #pragma unroll
            for (int r = 0; r < 4; r++) {
                acc[r][0] = ffma2(zB[r], eB[0], acc[r][0]);
                acc[r][1] = ffma2(zB[r], eB[1], acc[r][1]);
                acc[r][2] = ffma2(zB[r], eB[2], acc[r][2]);
                acc[r][3] = ffma2(zB[r], eB[3], acc[r][3]);
            }
        }
        __syncthreads();
    }

    if (t < TM) z2[t] = z2r;
    __syncthreads();   // z2 visible; stages dead -> reduction overlay safe

    // ---- alpha ----
    int ai = Alpha[0];
    float a = (ai > 0 && ai < 1000000) ? (float)ai : __int_as_float(ai);
    float inva = 1.0f / a;
    float coef = -(a + 1.0f) * 0.5f;

    // ---- epilogue: d, q, per-row local argmin + qsum ----
    float rmin[4], rsum[4];
    int   rid[4];
    #pragma unroll
    for (int r = 0; r < 4; r++) { rmin[r] = 3.4e38f; rsum[r] = 0.f; rid[r] = 0; }

    float z2v[4];
    #pragma unroll
    for (int r = 0; r < 4; r++) z2v[r] = z2[r0 + r];

    #pragma unroll
    for (int m = 0; m < 4; m++) {
        int j0 = 2 * cg + 64 * m, j1 = j0 + 1;
        float e20 = e2[j0], e21 = e2[j1];
        #pragma unroll
        for (int r = 0; r < 4; r++) {
            u64 av = acc[r][m];
            float dotl = __uint_as_float((unsigned)av);
            float doth = __uint_as_float((unsigned)(av >> 32));
            float dl = fmaxf(z2v[r] + e20 - 2.f * dotl, 0.f);
            float dh = fmaxf(z2v[r] + e21 - 2.f * doth, 0.f);
            float ql = exp2f(coef * __log2f(fmaf(dl, inva, 1.0f)));
            float qh = exp2f(coef * __log2f(fmaf(dh, inva, 1.0f)));
            if (dl < rmin[r]) { rmin[r] = dl; rid[r] = j0; }
            if (dh < rmin[r]) { rmin[r] = dh; rid[r] = j1; }
            rsum[r] += ql + qh;
            acc[r][m] = packf2(ql, qh);   // stash raw q
        }
    }
    #pragma unroll
    for (int r = 0; r < 4; r++) {
        int row = r0 + r;
        redv[row * REDS + cg] = rmin[r];
        redi[row * REDS + cg] = rid[r];
        reds[row * REDS + cg] = rsum[r];
    }
    __syncthreads();

    // ---- cross-lane reduction: bmu (lowest-index tie-break) + 1/qsum ----
    if (t < TM) {
        float bv = 3.4e38f; int bi = 0x7fffffff; float s = 0.f;
        #pragma unroll 4
        for (int g = 0; g < 32; g++) {
            float v = redv[t * REDS + g];
            int   i = redi[t * REDS + g];
            s += reds[t * REDS + g];
            if (v < bv || (v == bv && i < bi)) { bv = v; bi = i; }
        }
        bmuS[t] = bi;
        rqs[t]  = 1.0f / s;
    }
    __syncthreads();

    // ---- outputs: [z_q | z_q_neighbors | q | bmu] ----
    const size_t NBOFF  = (size_t)NROWS * 256;
    const size_t QOFF   = (size_t)NROWS * 1536;
    const size_t BMUOFF = (size_t)NROWS * 1792;

    // q: STG.64, lanes cover contiguous node pairs -> coalesced 256B per m
    #pragma unroll
    for (int r = 0; r < 4; r++) {
        int row = r0 + r;
        float rq = rqs[row];
        u64* dst = (u64*)(out + QOFF + (size_t)(R0 + row) * NNODES + 2 * cg);
        #pragma unroll
        for (int m = 0; m < 4; m++) {
            u64 av = acc[r][m];
            float ql = fmaf(__uint_as_float((unsigned)av),         rq, EPSF);
            float qh = fmaf(__uint_as_float((unsigned)(av >> 32)), rq, EPSF);
            dst[32 * m] = packf2(ql, qh);
        }
    }

    if (t < TM) out[BMUOFF + R0 + t] = (float)bmuS[t];

    // z_q + neighbor gathers: 6 copies/row, one warp per copy
    const int lane = t & 31, wid = t >> 5;
    for (int cp = wid; cp < TM * 6; cp += 16) {
        int row = cp / 6;
        int s   = cp - row * 6;
        int b   = bmuS[row];
        int idx;
        if (s <= 1) {
            idx = b;
        } else {
            int k1 = b >> 4, k2 = b & 15;
            if      (s == 2) idx = (((k1 + 15) & 15) << 4) + k2;   // up
            else if (s == 3) idx = (((k1 + 1)  & 15) << 4) + k2;   // down
            else if (s == 4) idx = (k1 << 4) + ((k2 + 1)  & 15);   // right
            else             idx = (k1 << 4) + ((k2 + 15) & 15);   // left
        }
        const float4* src = (const float4*)(E + (size_t)idx * LATENT);
        float4 a0 = src[lane], a1 = src[lane + 32];
        float* dstp = (s == 0)
            ? out + (size_t)(R0 + row) * LATENT
            : out + NBOFF + ((size_t)(R0 + row) * 5 + (s - 1)) * LATENT;
        float4* d4 = (float4*)dstp;
        d4[lane]      = a0;
        d4[lane + 32] = a1;
    }
}

extern "C" void kernel_launch(void* const* d_in, const int* in_sizes, int n_in,
                              void* d_out, int out_size) {
    const float* Z = (const float*)d_in[0];
    const float* E = (const float*)d_in[1];
    const int*   A = (const int*)d_in[2];
    float* out = (float*)d_out;

    cudaFuncSetAttribute(som_kernel, cudaFuncAttributeMaxDynamicSharedMemorySize, SMEM_BYTES);
    som_kernel<<<NROWS / TM, NT, SMEM_BYTES>>>(Z, E, A, out);
}